// round 14
// baseline (speedup 1.0000x reference)
#include <cuda_runtime.h>
#include <cuda_fp16.h>
#include <cstdint>
#include <cfloat>

#define BATCH 4
#define SEQ   2048
#define DMODEL 128
#define DLOW  16
#define NEGV  (-1e9f)
#define SCALE 0.25f
#define NQB   32

// ---- scratch (static __device__, no allocations) ----
__device__ __half g_S[BATCH * SEQ * SEQ];         // 32 MB: exp(corrected scores), fp16
__device__ float g_qlow[BATCH * SEQ * DLOW];
__device__ float g_klowT[BATCH * DLOW * SEQ];
__device__ float g_c[BATCH * SEQ];                // exp(correction score), exact fp32
__device__ float g_part[NQB][BATCH * SEQ];        // exact column-sum partials
__device__ float g_Zadj[BATCH * SEQ];
__device__ float g_cmax[BATCH * SEQ * 16];        // exact per-row per-128-chunk maxima
__device__ __half g_VT[BATCH * DMODEL * SEQ];     // (V*w)^T fp16, [b][d][k]

// ============================================================
// K1: projections. One block (64 threads) per (b, position).
// Also zeroes g_Zadj.
// ============================================================
__global__ void proj_kernel(const float* __restrict__ q, const float* __restrict__ k,
                            const float* __restrict__ Wql, const float* __restrict__ bql,
                            const float* __restrict__ Wkl, const float* __restrict__ bkl,
                            const float* __restrict__ Wqh, const float* __restrict__ bqh,
                            const float* __restrict__ Wkh, const float* __restrict__ bkh)
{
    int p = blockIdx.x;
    int b = p >> 11, i = p & (SEQ - 1);
    __shared__ float qs[DMODEL], ks[DMODEL];
    __shared__ float qh[DLOW], kh[DLOW];
    int t = threadIdx.x;
    if (t == 1) g_Zadj[p] = 0.f;
    {
        float2 qv = *(const float2*)&q[p * DMODEL + t * 2];
        qs[t * 2] = qv.x; qs[t * 2 + 1] = qv.y;
        float2 kv = *(const float2*)&k[p * DMODEL + t * 2];
        ks[t * 2] = kv.x; ks[t * 2 + 1] = kv.y;
    }
    __syncthreads();
    int j = t & 15;
    int which = t >> 4;
    const float* W; const float* bias; const float* src;
    if (which == 0)      { W = Wql; bias = bql; src = qs; }
    else if (which == 1) { W = Wkl; bias = bkl; src = ks; }
    else if (which == 2) { W = Wqh; bias = bqh; src = qs; }
    else                 { W = Wkh; bias = bkh; src = ks; }
    float acc = bias[j];
    #pragma unroll 16
    for (int d0 = 0; d0 < DMODEL; d0++)
        acc = fmaf(src[d0], W[d0 * DLOW + j], acc);
    if (which == 0)      g_qlow[p * DLOW + j] = acc;
    else if (which == 1) g_klowT[(b * DLOW + j) * SEQ + i] = acc;
    else if (which == 2) qh[j] = acc;
    else                 kh[j] = acc;
    __syncthreads();
    if (t == 0) {
        float c = 0.f;
        #pragma unroll
        for (int jj = 0; jj < DLOW; jj++) c = fmaf(qh[jj], kh[jj], c);
        g_c[p] = __expf(c * SCALE);
    }
}

// ============================================================
// K2a: exp(masked low-rank scores) -> fp16 S, exact fp32 column
// partial sums + exact per-row chunk maxima.
// ============================================================
__global__ void scores_kernel(const int* __restrict__ valid_lens)
{
    int b  = blockIdx.z;
    int q0 = blockIdx.y * 64;
    int k0 = blockIdx.x * 128;
    __shared__ float qT[DLOW][64];
    __shared__ float kS[DLOW][128];
    __shared__ float redsm[8][128];
    int t = threadIdx.x;
    {
        int row = t >> 2, j0 = (t & 3) * 4;
        const float4 v = *(const float4*)&g_qlow[(b * SEQ + q0 + row) * DLOW + j0];
        qT[j0 + 0][row] = v.x; qT[j0 + 1][row] = v.y;
        qT[j0 + 2][row] = v.z; qT[j0 + 3][row] = v.w;
    }
    {
        int row = t >> 5, c0 = (t & 31) * 4;
        #pragma unroll
        for (int r = 0; r < DLOW; r += 8)
            *(float4*)&kS[row + r][c0] =
                *(const float4*)&g_klowT[(b * DLOW + row + r) * SEQ + k0 + c0];
    }
    __syncthreads();
    int tx = t & 31, ty = t >> 5;
    int m0 = ty * 8, n0 = tx * 4;
    float acc[8][4];
    #pragma unroll
    for (int i = 0; i < 8; i++)
        #pragma unroll
        for (int jj = 0; jj < 4; jj++) acc[i][jj] = 0.f;
    #pragma unroll
    for (int j = 0; j < DLOW; j++) {
        float a[8];
        *(float4*)&a[0] = *(const float4*)&qT[j][m0];
        *(float4*)&a[4] = *(const float4*)&qT[j][m0 + 4];
        float4 bv = *(const float4*)&kS[j][n0];
        #pragma unroll
        for (int i = 0; i < 8; i++) {
            acc[i][0] = fmaf(a[i], bv.x, acc[i][0]);
            acc[i][1] = fmaf(a[i], bv.y, acc[i][1]);
            acc[i][2] = fmaf(a[i], bv.z, acc[i][2]);
            acc[i][3] = fmaf(a[i], bv.w, acc[i][3]);
        }
    }
    int vl[4];
    #pragma unroll
    for (int jj = 0; jj < 4; jj++) {
        int v = valid_lens[b * SEQ + k0 + n0 + jj];
        vl[jj] = min(max(v, 0), SEQ - 1);
    }
    float cs[4] = {0.f, 0.f, 0.f, 0.f};
    float rmax[8];
    #pragma unroll
    for (int i = 0; i < 8; i++) {
        int qrow = q0 + m0 + i;
        float e[4];
        float rm = -FLT_MAX;
        #pragma unroll
        for (int jj = 0; jj < 4; jj++) {
            float v = acc[i][jj] * SCALE;
            if (vl[jj] == qrow) v += NEGV;
            e[jj] = __expf(v);
            cs[jj] += e[jj];
            rm = fmaxf(rm, e[jj]);
        }
        rmax[i] = rm;
        __half2 h01 = __floats2half2_rn(e[0], e[1]);
        __half2 h23 = __floats2half2_rn(e[2], e[3]);
        uint2 pk = make_uint2(*(uint32_t*)&h01, *(uint32_t*)&h23);
        *(uint2*)&g_S[(b * SEQ + qrow) * SEQ + k0 + n0] = pk;
    }
    #pragma unroll
    for (int i = 0; i < 8; i++) {
        float rm = rmax[i];
        #pragma unroll
        for (int off = 16; off > 0; off >>= 1)
            rm = fmaxf(rm, __shfl_xor_sync(0xffffffffu, rm, off));
        if (tx == 0)
            g_cmax[(b * SEQ + q0 + m0 + i) * 16 + blockIdx.x] = rm;
    }
    #pragma unroll
    for (int jj = 0; jj < 4; jj++) redsm[ty][n0 + jj] = cs[jj];
    __syncthreads();
    if (t < 128) {
        float s = 0.f;
        #pragma unroll
        for (int r = 0; r < 8; r++) s += redsm[r][t];
        g_part[blockIdx.y][b * SEQ + k0 + t] = s;
    }
}

// ============================================================
// K2b: warp-per-row EXACT top-8 over fp16 storage.
// T = 8th-largest exact chunk max; gather fp16 candidates with a
// safety margin; recompute each candidate's EXACT fp32 score
// (bit-identical FMA order to scores_kernel); rank exactly.
// ============================================================
__global__ void __launch_bounds__(256) topk_kernel()
{
    __shared__ float cV[8][64];
    __shared__ int   cI[8][64];
    __shared__ int   cnt[8];
    int t = threadIdx.x, lane = t & 31, w = t >> 5;
    int row = blockIdx.x * 8 + w;                 // 0..8191
    int b = row >> 11;
    __half* Srow = &g_S[row * SEQ];

    // exact qlow row in registers (broadcast loads, L1/L2-hot)
    float ql[DLOW];
    #pragma unroll
    for (int j = 0; j < DLOW; j++) ql[j] = g_qlow[row * DLOW + j];

    auto recompute = [&](int kk) -> float {
        float acc = 0.f;
        #pragma unroll
        for (int j = 0; j < DLOW; j++)
            acc = fmaf(ql[j], g_klowT[(b * DLOW + j) * SEQ + kk], acc);
        return __expf(acc * SCALE);
    };

    // threshold from exact chunk maxima
    float cm0 = (lane < 16) ? g_cmax[row * 16 + lane] : -FLT_MAX;
    float a = cm0, T = cm0;
    #pragma unroll
    for (int it = 0; it < 8; it++) {
        float m = a;
        #pragma unroll
        for (int off = 16; off > 0; off >>= 1)
            m = fmaxf(m, __shfl_xor_sync(0xffffffffu, m, off));
        T = m;
        unsigned ba = __ballot_sync(0xffffffffu, a == m);
        if (lane == (int)(__ffs(ba) - 1)) a = -FLT_MAX;
    }
    float Tm = T * 0.999f;   // fp16 rounding margin (2^-11 < 1e-3)

    unsigned chunkmask = __ballot_sync(0xffffffffu, cm0 >= T) & 0xffffu;

    if (lane == 0) cnt[w] = 0;
    __syncwarp();
    unsigned mrem = chunkmask;
    while (mrem) {
        int c = __ffs(mrem) - 1;
        mrem &= mrem - 1;
        int off = c * 128 + lane * 4;
        uint2 pk = *(const uint2*)&Srow[off];
        __half2 h01 = *(__half2*)&pk.x;
        __half2 h23 = *(__half2*)&pk.y;
        float2 f01 = __half22float2(h01);
        float2 f23 = __half22float2(h23);
        float xv[4] = {f01.x, f01.y, f23.x, f23.y};
        float m4 = fmaxf(fmaxf(xv[0], xv[1]), fmaxf(xv[2], xv[3]));
        if (m4 >= Tm) {
            #pragma unroll
            for (int jj = 0; jj < 4; jj++) {
                if (xv[jj] >= Tm) {
                    int p = atomicAdd(&cnt[w], 1);
                    if (p < 64) cI[w][p] = off + jj;
                }
            }
        }
    }
    __syncwarp();
    int nc = cnt[w];

    int   chI[8];
    float chV[8];

    if (nc <= 64) {
        // exact recompute of candidate scores
        for (int p = lane; p < nc; p += 32)
            cV[w][p] = recompute(cI[w][p]);
        __syncwarp();
        #pragma unroll 1
        for (int it = 0; it < 8; it++) {
            float bv = -FLT_MAX; int bi = 0x7fffffff;
            for (int p = lane; p < nc; p += 32) {
                float cv = cV[w][p]; int ci = cI[w][p];
                if (cv > bv || (cv == bv && ci < bi)) { bv = cv; bi = ci; }
            }
            #pragma unroll
            for (int off = 16; off > 0; off >>= 1) {
                float ov = __shfl_xor_sync(0xffffffffu, bv, off);
                int   oi = __shfl_xor_sync(0xffffffffu, bi, off);
                if (ov > bv || (ov == bv && oi < bi)) { bv = ov; bi = oi; }
            }
            for (int p = lane; p < nc; p += 32)
                if (cI[w][p] == bi) cV[w][p] = -FLT_MAX;
            chI[it] = bi; chV[it] = bv;
        }
    } else {
        // exact slow path: global rescan with recompute (rare/never)
        #pragma unroll 1
        for (int it = 0; it < 8; it++) {
            float bv = -FLT_MAX; int bi = 0x7fffffff;
            for (int p = lane; p < SEQ; p += 32) {
                float v16 = __half2float(Srow[p]);
                if (v16 < Tm) continue;
                bool skip = false;
                #pragma unroll 8
                for (int x = 0; x < 8; x++)
                    if (x < it && chI[x] == p) skip = true;
                if (skip) continue;
                float cv = recompute(p);
                if (cv > bv || (cv == bv && p < bi)) { bv = cv; bi = p; }
            }
            #pragma unroll
            for (int off = 16; off > 0; off >>= 1) {
                float ov = __shfl_xor_sync(0xffffffffu, bv, off);
                int   oi = __shfl_xor_sync(0xffffffffu, bi, off);
                if (ov > bv || (ov == bv && oi < bi)) { bv = ov; bi = oi; }
            }
            chI[it] = bi; chV[it] = bv;
        }
    }

    if (lane == 0) {
        #pragma unroll
        for (int it = 0; it < 8; it++) {
            int bi = chI[it];
            float ec = g_c[b * SEQ + bi];
            Srow[bi] = __float2half_rn(ec);
            atomicAdd(&g_Zadj[b * SEQ + bi], ec - chV[it]);
        }
    }
}

// ============================================================
// K3: (V*w)^T -> fp16, [b][d][k]; finalize (w = 1/Z) fused.
// ============================================================
__global__ void vconv_kernel(const float* __restrict__ V)
{
    int b = blockIdx.y, k0 = blockIdx.x * 32;
    __shared__ float vs[32][129];
    __shared__ float wsh[32];
    int t = threadIdx.x;
    if (t < 32) {
        int idx = b * SEQ + k0 + t;
        float z = g_Zadj[idx];
        #pragma unroll
        for (int s = 0; s < NQB; s++) z += g_part[s][idx];
        wsh[t] = 1.0f / z;
    }
    __syncthreads();
    {
        int r = t >> 3, c0 = (t & 7) * 16;
        float wk = wsh[r];
        #pragma unroll
        for (int qd = 0; qd < 4; qd++) {
            float4 vv = *(const float4*)&V[(b * SEQ + k0 + r) * DMODEL + c0 + qd * 4];
            vs[r][c0 + qd * 4 + 0] = vv.x * wk;
            vs[r][c0 + qd * 4 + 1] = vv.y * wk;
            vs[r][c0 + qd * 4 + 2] = vv.z * wk;
            vs[r][c0 + qd * 4 + 3] = vv.w * wk;
        }
    }
    __syncthreads();
    int d = t >> 1, kh = (t & 1) * 16;
    __half2 hp[8];
    #pragma unroll
    for (int i = 0; i < 8; i++)
        hp[i] = __floats2half2_rn(vs[kh + 2 * i][d], vs[kh + 2 * i + 1][d]);
    __half* dst = &g_VT[(b * DMODEL + d) * SEQ + k0 + kh];
    *(uint4*)dst = ((uint4*)hp)[0];
    *((uint4*)dst + 1) = ((uint4*)hp)[1];
}

// ============================================================
// K4: fp16 tensor-core output GEMM (single term — no splits).
// Block 64q x 128d, BK=64, 8 warps as 2(m) x 4(n), warp tile 32x32,
// mma.sync.m16n8k16 fp16, double-buffered smem (raw fp16 copies).
// ============================================================
#define PSTH  72                       // smem k-stride (halves), conflict-free
#define P_SZH (64 * PSTH)              // 4608
#define V_SZH (128 * PSTH)             // 9216
#define BUFH  (P_SZH + V_SZH)          // 13824 halves per buffer
#define MMA_SMEM (2 * BUFH * 2)        // 55296 bytes

#define MMA_F16(c, a, bb) \
    asm volatile("mma.sync.aligned.m16n8k16.row.col.f32.f16.f16.f32 " \
        "{%0,%1,%2,%3}, {%4,%5,%6,%7}, {%8,%9}, {%0,%1,%2,%3};" \
        : "+f"((c)[0]), "+f"((c)[1]), "+f"((c)[2]), "+f"((c)[3]) \
        : "r"((a)[0]), "r"((a)[1]), "r"((a)[2]), "r"((a)[3]), \
          "r"((bb)[0]), "r"((bb)[1]))

__global__ void __launch_bounds__(256) out_gemm_mma(float* __restrict__ out)
{
    extern __shared__ __half smb[];
    int b = blockIdx.y, q0 = blockIdx.x * 64;
    int t = threadIdx.x, lane = t & 31, w = t >> 5;
    int g = lane >> 2, tq = lane & 3;
    int wm = w >> 2, wn = w & 3;

    const __half* Sbase = &g_S[(b * SEQ + q0) * SEQ];
    const __half* VTb   = &g_VT[b * DMODEL * SEQ];

    int pq = t >> 3, pk = (t & 7) * 8;      // loader coords (8 halves per uint4)

    float acc[2][4][4];
    #pragma unroll
    for (int mt = 0; mt < 2; mt++)
        #pragma unroll
        for (int nt = 0; nt < 4; nt++)
            #pragma unroll
            for (int x = 0; x < 4; x++) acc[mt][nt][x] = 0.f;

    uint4 sP[2], sV[4];

    auto LOADG = [&](int kt) {
        #pragma unroll
        for (int pass = 0; pass < 2; pass++)
            sP[pass] = *(const uint4*)&Sbase[(pq + pass * 32) * SEQ + kt + pk];
        #pragma unroll
        for (int pass = 0; pass < 4; pass++)
            sV[pass] = *(const uint4*)&VTb[(pq + pass * 32) * SEQ + kt + pk];
    };
    auto STORES = [&](int buf) {
        __half* Ph = smb + buf * BUFH;
        __half* Vh = Ph + P_SZH;
        #pragma unroll
        for (int pass = 0; pass < 2; pass++)
            *(uint4*)&Ph[(pq + pass * 32) * PSTH + pk] = sP[pass];
        #pragma unroll
        for (int pass = 0; pass < 4; pass++)
            *(uint4*)&Vh[(pq + pass * 32) * PSTH + pk] = sV[pass];
    };
    auto COMPUTE = [&](int buf) {
        const __half* Ph = smb + buf * BUFH;
        const __half* Vh = Ph + P_SZH;
        #pragma unroll
        for (int ks = 0; ks < 64; ks += 16) {
            uint32_t ah[2][4];
            #pragma unroll
            for (int mt = 0; mt < 2; mt++) {
                int r = (wm * 32 + mt * 16 + g) * PSTH + ks + 2 * tq;
                ah[mt][0] = *(const uint32_t*)&Ph[r];
                ah[mt][1] = *(const uint32_t*)&Ph[r + 8 * PSTH];
                ah[mt][2] = *(const uint32_t*)&Ph[r + 8];
                ah[mt][3] = *(const uint32_t*)&Ph[r + 8 * PSTH + 8];
            }
            uint32_t bh[4][2];
            #pragma unroll
            for (int nt = 0; nt < 4; nt++) {
                int r = (wn * 32 + nt * 8 + g) * PSTH + ks + 2 * tq;
                bh[nt][0] = *(const uint32_t*)&Vh[r];
                bh[nt][1] = *(const uint32_t*)&Vh[r + 8];
            }
            #pragma unroll
            for (int mt = 0; mt < 2; mt++)
                #pragma unroll
                for (int nt = 0; nt < 4; nt++)
                    MMA_F16(acc[mt][nt], ah[mt], bh[nt]);
        }
    };

    LOADG(0);
    STORES(0);
    __syncthreads();
    const int NKT = SEQ / 64;
    for (int kt_i = 0; kt_i < NKT; kt_i++) {
        if (kt_i + 1 < NKT) LOADG((kt_i + 1) * 64);
        COMPUTE(kt_i & 1);
        if (kt_i + 1 < NKT) STORES((kt_i & 1) ^ 1);
        __syncthreads();
    }

    #pragma unroll
    for (int mt = 0; mt < 2; mt++)
        #pragma unroll
        for (int nt = 0; nt < 4; nt++) {
            int qq = q0 + wm * 32 + mt * 16 + g;
            int dd = wn * 32 + nt * 8 + 2 * tq;
            *(float2*)&out[(b * SEQ + qq) * DMODEL + dd] =
                make_float2(acc[mt][nt][0], acc[mt][nt][1]);
            *(float2*)&out[(b * SEQ + qq + 8) * DMODEL + dd] =
                make_float2(acc[mt][nt][2], acc[mt][nt][3]);
        }
}

// ============================================================
extern "C" void kernel_launch(void* const* d_in, const int* in_sizes, int n_in,
                              void* d_out, int out_size)
{
    const float* queries = (const float*)d_in[0];
    const float* keys    = (const float*)d_in[1];
    const float* values  = (const float*)d_in[2];
    const int*   vlens   = (const int*)  d_in[3];
    const float* Wql     = (const float*)d_in[4];
    const float* bql     = (const float*)d_in[5];
    const float* Wkl     = (const float*)d_in[6];
    const float* bkl     = (const float*)d_in[7];
    const float* Wqh     = (const float*)d_in[8];
    const float* bqh     = (const float*)d_in[9];
    const float* Wkh     = (const float*)d_in[10];
    const float* bkh     = (const float*)d_in[11];
    float* out = (float*)d_out;

    static bool attr_set = false;
    if (!attr_set) {
        cudaFuncSetAttribute(out_gemm_mma,
                             cudaFuncAttributeMaxDynamicSharedMemorySize, MMA_SMEM);
        attr_set = true;
    }

    proj_kernel<<<BATCH * SEQ, 64>>>(queries, keys, Wql, bql, Wkl, bkl,
                                     Wqh, bqh, Wkh, bkh);
    scores_kernel<<<dim3(SEQ / 128, SEQ / 64, BATCH), 256>>>(vlens);
    topk_kernel<<<BATCH * SEQ / 8, 256>>>();
    vconv_kernel<<<dim3(SEQ / 32, BATCH), 256>>>(values);
    out_gemm_mma<<<dim3(SEQ / 64, BATCH), 256, MMA_SMEM>>>(out);
}